// round 15
// baseline (speedup 1.0000x reference)
#include <cuda_runtime.h>
#include <cstdint>

// MoE gating, exact fp32, K-packed f32x2 GEMM, XOR-swizzled staging (SW-16B).
// x:[16384,1024] f32, gate_w:[64,1024] f32.
// out (f32): top_scores [T,2] | top_idx [T,2] | total_loss [1].

#define H      1024
#define NE     64
#define TM     128
#define NT     256
#define KC     32
#define NSTEP  16                  // 512 k per half / KC
#define XLo    0
#define XHi    4096                // 128 rows x 32 floats
#define WLo    8192
#define WHi    10240               // 64 rows x 32 floats
#define STG    12288               // floats / stage (48 KB)
#define DSMEM  (3 * STG * 4)       // 147456 B
#define SPS    65
#define NBLK   128

__device__ float    g_pexp[NBLK * NE];
__device__ float    g_pz2[NBLK];
__device__ unsigned g_cnt = 0;

typedef unsigned long long ull;

__device__ __forceinline__ void fma2(ull& d, ull a, ull b) {
    asm("fma.rn.f32x2 %0, %1, %2, %0;" : "+l"(d) : "l"(a), "l"(b));
}
__device__ __forceinline__ uint32_t su32(const void* p) {
    uint32_t a;
    asm("{ .reg .u64 t; cvta.to.shared.u64 t, %1; cvt.u32.u64 %0, t; }"
        : "=r"(a) : "l"(p));
    return a;
}
__device__ __forceinline__ void cpa16(uint32_t dst, const float* src) {
    asm volatile("cp.async.cg.shared.global [%0], [%1], 16;" :: "r"(dst), "l"(src));
}

__global__ void __launch_bounds__(NT, 1) moe_gate(const float* __restrict__ x,
                                                  const float* __restrict__ w,
                                                  float* __restrict__ out,
                                                  int T) {
    extern __shared__ __align__(16) float dsm[];
    __shared__ float    s_red[8];
    __shared__ unsigned s_last;

    const int tid  = threadIdx.x;
    const int wid  = tid >> 5;
    const int lid  = tid & 31;
    const int tBlk = blockIdx.x * TM;
    const uint32_t sb = su32(dsm);

    // compute map (as R13)
    const int khalf = wid >> 2;            // 0: k<512, 1: k>=512
    const int wq    = wid & 3;
    const int tx    = lid & 7;             // experts {tx+8j}
    const int ty    = lid >> 3;
    const int g     = wq * 4 + ty;         // tokens {g+16i}
    const int ra7   = g & 7;               // swizzle phase for a-rows

    ull acc[8][8];
#pragma unroll
    for (int i = 0; i < 8; i++)
#pragma unroll
        for (int j = 0; j < 8; j++) acc[i][j] = 0ull;

    // staging: quad (row, sq) stored at chunk position sq ^ (row & 7)
#define STAGE(s_, slot_) do {                                                    \
    int _k0 = (s_) * KC;                                                         \
    uint32_t _sb = sb + (slot_) * (STG * 4);                                     \
    _Pragma("unroll")                                                            \
    for (int r = 0; r < 4; r++) {                                                \
        int idx = r * 256 + tid;                                                 \
        int t_ = idx >> 3, sq_ = idx & 7;                                        \
        int doff = t_ * 32 + (((sq_ ^ t_) & 7) << 2);                            \
        const float* srcL = x + (size_t)(tBlk + t_) * H + _k0 + sq_ * 4;         \
        cpa16(_sb + (XLo + doff) * 4, srcL);                                     \
        cpa16(_sb + (XHi + doff) * 4, srcL + 512);                               \
    }                                                                            \
    _Pragma("unroll")                                                            \
    for (int r = 0; r < 2; r++) {                                                \
        int idx = r * 256 + tid;                                                 \
        int e_ = idx >> 3, sq_ = idx & 7;                                        \
        int doff = e_ * 32 + (((sq_ ^ e_) & 7) << 2);                            \
        const float* srcW = w + (size_t)e_ * H + _k0 + sq_ * 4;                  \
        cpa16(_sb + (WLo + doff) * 4, srcW);                                     \
        cpa16(_sb + (WHi + doff) * 4, srcW + 512);                               \
    }                                                                            \
} while (0)

    // prologue: fill stages 0 and 1
    STAGE(0, 0);
    asm volatile("cp.async.commit_group;" ::: "memory");
    STAGE(1, 1);
    asm volatile("cp.async.commit_group;" ::: "memory");

#pragma unroll 1
    for (int s = 0; s < NSTEP; s++) {
        asm volatile("cp.async.wait_group 1;" ::: "memory");
        __syncthreads();
        if (s + 2 < NSTEP) STAGE(s + 2, (s + 2) % 3);
        asm volatile("cp.async.commit_group;" ::: "memory");

        const float* xs = dsm + (s % 3) * STG + (khalf ? XHi : XLo) + g * 32;
        const float* ws = dsm + (s % 3) * STG + (khalf ? WHi : WLo) + tx * 32;

        // 8 pair-blocks; chunk blk of row r lives at position blk ^ (r&7)
#pragma unroll
        for (int blk = 0; blk < 8; blk++) {
            const int cA = (blk ^ ra7) << 2;
            const int cB = (blk ^ tx) << 2;
            ulonglong2 a[8], b[8];
#pragma unroll
            for (int i = 0; i < 8; i++)
                a[i] = *(const ulonglong2*)(xs + i * 16 * 32 + cA);
#pragma unroll
            for (int j = 0; j < 8; j++)
                b[j] = *(const ulonglong2*)(ws + j * 8 * 32 + cB);
#pragma unroll
            for (int i = 0; i < 8; i++)
#pragma unroll
                for (int j = 0; j < 8; j++)
                    fma2(acc[i][j], a[i].x, b[j].x);
#pragma unroll
            for (int i = 0; i < 8; i++)
#pragma unroll
                for (int j = 0; j < 8; j++)
                    fma2(acc[i][j], a[i].y, b[j].y);
        }
    }
    __syncthreads();

    // ---- merge k-halves: logits -> sP[128][SPS] ----
    float* sP    = dsm;
    float* sInv  = dsm + 128 * SPS;        // 128
    float* sLoad = sInv + 128;             // [4][64]
    if (khalf == 0) {
#pragma unroll
        for (int i = 0; i < 8; i++)
#pragma unroll
            for (int j = 0; j < 8; j++) {
                float2 f = *(float2*)&acc[i][j];
                sP[(g + 16 * i) * SPS + tx + 8 * j] = f.x + f.y;
            }
    }
    __syncthreads();
    if (khalf == 1) {
#pragma unroll
        for (int i = 0; i < 8; i++)
#pragma unroll
            for (int j = 0; j < 8; j++) {
                float2 f = *(float2*)&acc[i][j];
                sP[(g + 16 * i) * SPS + tx + 8 * j] += f.x + f.y;
            }
    }
    __syncthreads();

    // ---- per-token softmax / top-2 ----
    float zsq = 0.0f;
    if (tid < TM) {
        float* row = sP + tid * SPS;
        float b1v = -1e30f, b2v = -1e30f;
        int   i1 = 0, i2 = 0;
#pragma unroll 8
        for (int e = 0; e < NE; e++) {
            float l = row[e];
            if (l > b1v)      { b2v = b1v; i2 = i1; b1v = l; i1 = e; }
            else if (l > b2v) { b2v = l;  i2 = e; }
        }
        float m = b1v, sum = 0.0f;
#pragma unroll 8
        for (int e = 0; e < NE; e++) {
            float ex = __expf(row[e] - m);
            sum += ex;
            row[e] = ex;
        }
        float inv = 1.0f / sum;
        sInv[tid] = inv;
        float z = m + __logf(sum);
        zsq = z * z;
        float p1 = __expf(b1v - m) * inv;
        float p2 = __expf(b2v - m) * inv;
        float dd = __expf(p2 - p1);
        int gt = tBlk + tid;
        out[2 * gt]             = 1.0f / (1.0f + dd);
        out[2 * gt + 1]         = dd / (1.0f + dd);
        out[2 * T + 2 * gt]     = (float)i1;
        out[2 * T + 2 * gt + 1] = (float)i2;
    }

    // ---- z-loss partial ----
#pragma unroll
    for (int off = 16; off > 0; off >>= 1)
        zsq += __shfl_down_sync(0xffffffffu, zsq, off);
    if (lid == 0) s_red[wid] = zsq;
    __syncthreads();
    if (tid == 0) {
        float s = 0.0f;
#pragma unroll
        for (int i = 0; i < 8; i++) s += s_red[i];
        g_pz2[blockIdx.x] = s;
    }

    // ---- expert-load partial, parallel over all 256 threads ----
    {
        int e = tid & 63, q = tid >> 6;
        float s = 0.0f;
#pragma unroll 8
        for (int t = 0; t < 32; t++) {
            int tok = q * 32 + t;
            s += sP[tok * SPS + e] * sInv[tok];
        }
        sLoad[q * 64 + e] = s;
    }
    __syncthreads();
    if (tid < NE)
        g_pexp[blockIdx.x * NE + tid] = sLoad[tid] + sLoad[64 + tid]
                                      + sLoad[128 + tid] + sLoad[192 + tid];

    // ---- fused finalize ----
    __threadfence();
    __syncthreads();
    if (tid == 0)
        s_last = (atomicAdd(&g_cnt, 1u) == (unsigned)(gridDim.x - 1)) ? 1u : 0u;
    __syncthreads();
    if (s_last) {
        __threadfence();
        int e = tid & 63, part = tid >> 6;
        float s = 0.0f;
#pragma unroll 4
        for (int b = part; b < NBLK; b += 4) s += g_pexp[b * NE + e];
        float z2 = (tid < NBLK) ? g_pz2[tid] : 0.0f;
        __syncthreads();
        float* redA = dsm;
        float* redZ = dsm + 256;
        redA[part * 64 + e] = s;
        redZ[tid] = z2;
        __syncthreads();
        if (tid < 64) {
            float load = (redA[tid] + redA[64 + tid] + redA[128 + tid] + redA[192 + tid]) / (float)T;
            float dv = load - 1.0f / 64.0f;
            float lb = dv * dv;
            float zz = redZ[tid] + redZ[tid + 64] + redZ[tid + 128] + redZ[tid + 192];
#pragma unroll
            for (int off = 16; off > 0; off >>= 1) {
                lb += __shfl_down_sync(0xffffffffu, lb, off);
                zz += __shfl_down_sync(0xffffffffu, zz, off);
            }
            if (lid == 0) { s_red[wid] = lb; s_red[4 + wid] = zz; }
        }
        __syncthreads();
        if (tid == 0) {
            out[4 * T] = 0.01f * 64.0f * (s_red[0] + s_red[1])
                       + 1e-4f * ((s_red[4] + s_red[5]) / (float)T);
            g_cnt = 0;
        }
    }
}

extern "C" void kernel_launch(void* const* d_in, const int* in_sizes, int n_in,
                              void* d_out, int out_size) {
    const float* x = (const float*)d_in[0];
    const float* w = (const float*)d_in[1];
    float* out = (float*)d_out;
    int T = in_sizes[0] / H;   // 16384
    cudaFuncSetAttribute(moe_gate, cudaFuncAttributeMaxDynamicSharedMemorySize, DSMEM);
    moe_gate<<<T / TM, NT, DSMEM>>>(x, w, out, T);   // grid = 128
}

// round 16
// speedup vs baseline: 1.0996x; 1.0996x over previous
#include <cuda_runtime.h>
#include <cstdint>

// MoE gating, exact fp32, K-packed f32x2 GEMM. R13 core with KC=64 (8 steps).
// x:[16384,1024] f32, gate_w:[64,1024] f32.
// out (f32): top_scores [T,2] | top_idx [T,2] | total_loss [1].

#define H      1024
#define NE     64
#define TM     128
#define NT     256
#define KC     64
#define NSTEP  8                   // 512 k per half / KC
#define RS     68                  // smem row stride (floats), 16B-aligned
#define XLo    0
#define XHi    (128 * RS)          // 8704
#define WLo    (256 * RS)          // 17408
#define WHi    (WLo + 64 * RS)     // 21760
#define STG    (WHi + 64 * RS)     // 26112 floats / stage
#define DSMEM  (2 * STG * 4)       // 208896 B
#define SPS    65
#define NBLK   128

__device__ float    g_pexp[NBLK * NE];
__device__ float    g_pz2[NBLK];
__device__ unsigned g_cnt = 0;

typedef unsigned long long ull;

__device__ __forceinline__ void fma2(ull& d, ull a, ull b) {
    asm("fma.rn.f32x2 %0, %1, %2, %0;" : "+l"(d) : "l"(a), "l"(b));
}
__device__ __forceinline__ uint32_t su32(const void* p) {
    uint32_t a;
    asm("{ .reg .u64 t; cvta.to.shared.u64 t, %1; cvt.u32.u64 %0, t; }"
        : "=r"(a) : "l"(p));
    return a;
}
__device__ __forceinline__ void cpa16(uint32_t dst, const float* src) {
    asm volatile("cp.async.cg.shared.global [%0], [%1], 16;" :: "r"(dst), "l"(src));
}

__global__ void __launch_bounds__(NT, 1) moe_gate(const float* __restrict__ x,
                                                  const float* __restrict__ w,
                                                  float* __restrict__ out,
                                                  int T) {
    extern __shared__ __align__(16) float dsm[];
    __shared__ float    s_red[8];
    __shared__ unsigned s_last;

    const int tid  = threadIdx.x;
    const int wid  = tid >> 5;
    const int lid  = tid & 31;
    const int tBlk = blockIdx.x * TM;
    const uint32_t sb = su32(dsm);

    // compute map (as R13): khalf warp split
    const int khalf = wid >> 2;            // 0: k<512, 1: k>=512
    const int wq    = wid & 3;
    const int tx    = lid & 7;             // experts {tx+8j}
    const int ty    = lid >> 3;
    const int g     = wq * 4 + ty;         // tokens {g+16i}

    ull acc[8][8];
#pragma unroll
    for (int i = 0; i < 8; i++)
#pragma unroll
        for (int j = 0; j < 8; j++) acc[i][j] = 0ull;

    // staging: 16 quads (64 floats) per row, rows padded to RS floats
#define STAGE(s_, slot_) do {                                                    \
    int _k0 = (s_) * KC;                                                         \
    uint32_t _sb = sb + (slot_) * (STG * 4);                                     \
    _Pragma("unroll")                                                            \
    for (int r = 0; r < 8; r++) {                                                \
        int idx = r * 256 + tid;                                                 \
        int t_ = idx >> 4, q_ = idx & 15;                                        \
        const float* srcL = x + (size_t)(tBlk + t_) * H + _k0 + q_ * 4;          \
        cpa16(_sb + (XLo + t_ * RS + q_ * 4) * 4, srcL);                         \
        cpa16(_sb + (XHi + t_ * RS + q_ * 4) * 4, srcL + 512);                   \
    }                                                                            \
    _Pragma("unroll")                                                            \
    for (int r = 0; r < 4; r++) {                                                \
        int idx = r * 256 + tid;                                                 \
        int e_ = idx >> 4, q_ = idx & 15;                                        \
        const float* srcW = w + (size_t)e_ * H + _k0 + q_ * 4;                   \
        cpa16(_sb + (WLo + e_ * RS + q_ * 4) * 4, srcW);                         \
        cpa16(_sb + (WHi + e_ * RS + q_ * 4) * 4, srcW + 512);                   \
    }                                                                            \
} while (0)

    // prologue
    STAGE(0, 0);
    asm volatile("cp.async.commit_group;" ::: "memory");

#pragma unroll 1
    for (int s = 0; s < NSTEP; s++) {
        asm volatile("cp.async.wait_group 0;" ::: "memory");
        __syncthreads();
        if (s + 1 < NSTEP) STAGE(s + 1, (s + 1) & 1);
        asm volatile("cp.async.commit_group;" ::: "memory");

        const float* xs = dsm + (s & 1) * STG + (khalf ? XHi : XLo) + g * RS;
        const float* ws = dsm + (s & 1) * STG + (khalf ? WHi : WLo) + tx * RS;

        // 16 pair-blocks; each ulonglong2 = k-pairs (2blk, 2blk+1)
#pragma unroll 8
        for (int blk = 0; blk < 16; blk++) {
            ulonglong2 a[8], b[8];
#pragma unroll
            for (int i = 0; i < 8; i++)
                a[i] = *(const ulonglong2*)(xs + i * 16 * RS + 4 * blk);
#pragma unroll
            for (int j = 0; j < 8; j++)
                b[j] = *(const ulonglong2*)(ws + j * 8 * RS + 4 * blk);
#pragma unroll
            for (int i = 0; i < 8; i++)
#pragma unroll
                for (int j = 0; j < 8; j++)
                    fma2(acc[i][j], a[i].x, b[j].x);
#pragma unroll
            for (int i = 0; i < 8; i++)
#pragma unroll
                for (int j = 0; j < 8; j++)
                    fma2(acc[i][j], a[i].y, b[j].y);
        }
    }
    __syncthreads();

    // ---- merge k-halves: logits -> sP[128][SPS] ----
    float* sP    = dsm;
    float* sInv  = dsm + 128 * SPS;        // 128
    float* sLoad = sInv + 128;             // [4][64]
    if (khalf == 0) {
#pragma unroll
        for (int i = 0; i < 8; i++)
#pragma unroll
            for (int j = 0; j < 8; j++) {
                float2 f = *(float2*)&acc[i][j];
                sP[(g + 16 * i) * SPS + tx + 8 * j] = f.x + f.y;
            }
    }
    __syncthreads();
    if (khalf == 1) {
#pragma unroll
        for (int i = 0; i < 8; i++)
#pragma unroll
            for (int j = 0; j < 8; j++) {
                float2 f = *(float2*)&acc[i][j];
                sP[(g + 16 * i) * SPS + tx + 8 * j] += f.x + f.y;
            }
    }
    __syncthreads();

    // ---- per-token softmax / top-2 ----
    float zsq = 0.0f;
    if (tid < TM) {
        float* row = sP + tid * SPS;
        float b1v = -1e30f, b2v = -1e30f;
        int   i1 = 0, i2 = 0;
#pragma unroll 8
        for (int e = 0; e < NE; e++) {
            float l = row[e];
            if (l > b1v)      { b2v = b1v; i2 = i1; b1v = l; i1 = e; }
            else if (l > b2v) { b2v = l;  i2 = e; }
        }
        float m = b1v, sum = 0.0f;
#pragma unroll 8
        for (int e = 0; e < NE; e++) {
            float ex = __expf(row[e] - m);
            sum += ex;
            row[e] = ex;
        }
        float inv = 1.0f / sum;
        sInv[tid] = inv;
        float z = m + __logf(sum);
        zsq = z * z;
        float p1 = __expf(b1v - m) * inv;
        float p2 = __expf(b2v - m) * inv;
        float dd = __expf(p2 - p1);
        int gt = tBlk + tid;
        out[2 * gt]             = 1.0f / (1.0f + dd);
        out[2 * gt + 1]         = dd / (1.0f + dd);
        out[2 * T + 2 * gt]     = (float)i1;
        out[2 * T + 2 * gt + 1] = (float)i2;
    }

    // ---- z-loss partial ----
#pragma unroll
    for (int off = 16; off > 0; off >>= 1)
        zsq += __shfl_down_sync(0xffffffffu, zsq, off);
    if (lid == 0) s_red[wid] = zsq;
    __syncthreads();
    if (tid == 0) {
        float s = 0.0f;
#pragma unroll
        for (int i = 0; i < 8; i++) s += s_red[i];
        g_pz2[blockIdx.x] = s;
    }

    // ---- expert-load partial, parallel over all 256 threads ----
    {
        int e = tid & 63, q = tid >> 6;
        float s = 0.0f;
#pragma unroll 8
        for (int t = 0; t < 32; t++) {
            int tok = q * 32 + t;
            s += sP[tok * SPS + e] * sInv[tok];
        }
        sLoad[q * 64 + e] = s;
    }
    __syncthreads();
    if (tid < NE)
        g_pexp[blockIdx.x * NE + tid] = sLoad[tid] + sLoad[64 + tid]
                                      + sLoad[128 + tid] + sLoad[192 + tid];

    // ---- fused finalize ----
    __threadfence();
    __syncthreads();
    if (tid == 0)
        s_last = (atomicAdd(&g_cnt, 1u) == (unsigned)(gridDim.x - 1)) ? 1u : 0u;
    __syncthreads();
    if (s_last) {
        __threadfence();
        int e = tid & 63, part = tid >> 6;
        float s = 0.0f;
#pragma unroll 4
        for (int b = part; b < NBLK; b += 4) s += g_pexp[b * NE + e];
        float z2 = (tid < NBLK) ? g_pz2[tid] : 0.0f;
        __syncthreads();
        float* redA = dsm;
        float* redZ = dsm + 256;
        redA[part * 64 + e] = s;
        redZ[tid] = z2;
        __syncthreads();
        if (tid < 64) {
            float load = (redA[tid] + redA[64 + tid] + redA[128 + tid] + redA[192 + tid]) / (float)T;
            float dv = load - 1.0f / 64.0f;
            float lb = dv * dv;
            float zz = redZ[tid] + redZ[tid + 64] + redZ[tid + 128] + redZ[tid + 192];
#pragma unroll
            for (int off = 16; off > 0; off >>= 1) {
                lb += __shfl_down_sync(0xffffffffu, lb, off);
                zz += __shfl_down_sync(0xffffffffu, zz, off);
            }
            if (lid == 0) { s_red[wid] = lb; s_red[4 + wid] = zz; }
        }
        __syncthreads();
        if (tid == 0) {
            out[4 * T] = 0.01f * 64.0f * (s_red[0] + s_red[1])
                       + 1e-4f * ((s_red[4] + s_red[5]) / (float)T);
            g_cnt = 0;
        }
    }
}

extern "C" void kernel_launch(void* const* d_in, const int* in_sizes, int n_in,
                              void* d_out, int out_size) {
    const float* x = (const float*)d_in[0];
    const float* w = (const float*)d_in[1];
    float* out = (float*)d_out;
    int T = in_sizes[0] / H;   // 16384
    cudaFuncSetAttribute(moe_gate, cudaFuncAttributeMaxDynamicSharedMemorySize, DSMEM);
    moe_gate<<<T / TM, NT, DSMEM>>>(x, w, out, T);   // grid = 128
}